// round 11
// baseline (speedup 1.0000x reference)
#include <cuda_runtime.h>
#include <math.h>

#define NN   50000
#define EE   1600000
#define ETOT (EE + NN)   // edges + self-loops
#define GG   512
#define HC   32          // H*C

// ---------------- scratch (device globals) ----------------------------------
__device__ __align__(16) float g_deg  [NN];
__device__ __align__(16) float g_xcur [NN * HC];
__device__ __align__(16) float g_xl   [NN * HC];
__device__ __align__(16) float g_xr   [NN * HC];
__device__ __align__(16) float g_out  [NN * HC];
__device__ __align__(16) float g_denom[NN * 2];
__device__ __align__(16) int2  g_sd   [ETOT];     // (src,dst) incl. self-loops
__device__ __align__(16) float g_p    [HC];       // 0.6 * att
__device__ __align__(16) float g_q    [HC];       // 0.4 * att
__device__ __align__(16) float g_sums [GG * HC];
__device__ __align__(16) float g_cnt  [GG];

static inline int div_up(int a, int b) { return (a + b - 1) / b; }

// ---------------- f32x2 helpers ----------------------------------------------
typedef unsigned long long u64;

__device__ __forceinline__ u64 add2(u64 a, u64 b) {
    u64 r; asm("add.rn.f32x2 %0,%1,%2;" : "=l"(r) : "l"(a), "l"(b)); return r;
}
__device__ __forceinline__ u64 mul2(u64 a, u64 b) {
    u64 r; asm("mul.rn.f32x2 %0,%1,%2;" : "=l"(r) : "l"(a), "l"(b)); return r;
}
__device__ __forceinline__ u64 fma2(u64 a, u64 b, u64 c) {
    u64 r; asm("fma.rn.f32x2 %0,%1,%2,%3;" : "=l"(r) : "l"(a), "l"(b), "l"(c)); return r;
}
__device__ __forceinline__ float pairsum(u64 v) {
    float lo, hi;
    asm("mov.b64 {%0,%1},%2;" : "=f"(lo), "=f"(hi) : "l"(v));
    return lo + hi;
}
__device__ __forceinline__ u64 pack2(float x) {
    u64 r; asm("mov.b64 %0,{%1,%1};" : "=l"(r) : "f"(x)); return r;
}
__device__ __forceinline__ void red4p(float* p, u64 v01, u64 v23) {
    asm volatile("{\n\t"
                 ".reg .f32 f0,f1,f2,f3;\n\t"
                 "mov.b64 {f0,f1},%1;\n\t"
                 "mov.b64 {f2,f3},%2;\n\t"
                 "red.global.add.v4.f32 [%0],{f0,f1,f2,f3};\n\t"
                 "}" :: "l"(p), "l"(v01), "l"(v23) : "memory");
}

// ---------------- prep -------------------------------------------------------

__global__ void k_zero() {
    int i = blockIdx.x * blockDim.x + threadIdx.x;
    if (i < NN) g_deg[i] = 0.f;
}

__global__ void k_degree(const int* __restrict__ ei) {
    int e = blockIdx.x * blockDim.x + threadIdx.x;
    if (e < EE) {
        atomicAdd(&g_deg[ei[e]], 1.f);
        atomicAdd(&g_deg[ei[EE + e]], 1.f);
    }
}

// pack (src,dst) pairs, appending self-loops
__global__ void k_sd(const int* __restrict__ ei) {
    int e = blockIdx.x * blockDim.x + threadIdx.x;
    if (e < EE)        g_sd[e] = make_int2(ei[e], ei[EE + e]);
    else if (e < ETOT) { int n = e - EE; g_sd[e] = make_int2(n, n); }
}

// p = 0.6*att, q = 0.4*att  (leaky(m) = 0.6m + 0.4|m|)
__global__ void k_pq(const float* __restrict__ att) {
    int i = threadIdx.x;
    if (i < HC) { g_p[i] = 0.6f * att[i]; g_q[i] = 0.4f * att[i]; }
}

// conv1 linear with features [1, deg, rand] built inline; also zeroes out/denom
__global__ void k_lin3(const float* __restrict__ rf,
                       const float* __restrict__ Wl, const float* __restrict__ bl,
                       const float* __restrict__ Wr, const float* __restrict__ br) {
    int t = blockIdx.x * blockDim.x + threadIdx.x;
    if (t >= NN * HC) return;
    int n = t >> 5, o = t & 31;
    float x1 = g_deg[n], x2 = rf[n];
    g_xl[t] = bl[o] + Wl[o * 3] + Wl[o * 3 + 1] * x1 + Wl[o * 3 + 2] * x2;
    g_xr[t] = br[o] + Wr[o * 3] + Wr[o * 3 + 1] * x1 + Wr[o * 3 + 2] * x2;
    g_out[t] = 0.f;
    if (o < 2) g_denom[n * 2 + o] = 0.f;
}

// 32-in linear via warp shuffle broadcast (warp = node, lane = out channel)
__global__ void k_lin32(const float* __restrict__ Wl, const float* __restrict__ bl,
                        const float* __restrict__ Wr, const float* __restrict__ br) {
    int t = blockIdx.x * blockDim.x + threadIdx.x;
    if (t >= NN * HC) return;
    int o = t & 31;
    float xv = g_xcur[t];
    float al = bl[o], ar = br[o];
#pragma unroll
    for (int k = 0; k < 32; k++) {
        float xk = __shfl_sync(0xffffffffu, xv, k);
        al += Wl[o * 32 + k] * xk;
        ar += Wr[o * 32 + k] * xk;
    }
    g_xl[t] = al;
    g_xr[t] = ar;
}

// ---------------- fused conv edge pass ---------------------------------------
// 4 lanes per edge; lane j handles channels 8j..8j+7 (head = j>>1).
// score = sum_c p_c*m_c + q_c*|m_c|  (== sum att_c * leaky(m_c)), f32x2-packed.
// exp(clamp(score)) -> unnormalized aggregate (red.v4) + denom atomics.
__global__ void __launch_bounds__(256) k_conv_fused() {
    int t = blockIdx.x * blockDim.x + threadIdx.x;
    int e = t >> 2;
    if (e >= ETOT) return;
    int j = t & 3;
    int2 sd = g_sd[e];

    const ulonglong2* xl16 = (const ulonglong2*)g_xl;
    const ulonglong2* xr16 = (const ulonglong2*)g_xr;
    const ulonglong2* pp   = (const ulonglong2*)g_p;
    const ulonglong2* qq   = (const ulonglong2*)g_q;

    ulonglong2 A0 = xl16[sd.x * 8 + 2 * j], A1 = xl16[sd.x * 8 + 2 * j + 1];
    ulonglong2 B0 = xr16[sd.y * 8 + 2 * j], B1 = xr16[sd.y * 8 + 2 * j + 1];
    ulonglong2 P0 = pp[2 * j], P1 = pp[2 * j + 1];
    ulonglong2 Q0 = qq[2 * j], Q1 = qq[2 * j + 1];

    u64 m0 = add2(A0.x, B0.x), m1 = add2(A0.y, B0.y);
    u64 m2 = add2(A1.x, B1.x), m3 = add2(A1.y, B1.y);
    const u64 ABS = 0x7fffffff7fffffffULL;
    u64 v = mul2(Q0.x, m0 & ABS);
    v = fma2(P0.x, m0, v);
    v = fma2(Q0.y, m1 & ABS, v);
    v = fma2(P0.y, m1, v);
    v = fma2(Q1.x, m2 & ABS, v);
    v = fma2(P1.x, m2, v);
    v = fma2(Q1.y, m3 & ABS, v);
    v = fma2(P1.y, m3, v);

    float vs = pairsum(v);
    vs += __shfl_xor_sync(0xffffffffu, vs, 1);   // pairs (0,1)=head0, (2,3)=head1
    vs = fminf(fmaxf(vs, -60.f), 60.f);
    float ex = __expf(vs);

    u64 exx = pack2(ex);
    float* dst = &g_out[sd.y * HC + 8 * j];
    red4p(dst,     mul2(A0.x, exx), mul2(A0.y, exx));
    red4p(dst + 4, mul2(A1.x, exx), mul2(A1.y, exx));
    if ((j & 1) == 0)
        atomicAdd(&g_denom[sd.y * 2 + (j >> 1)], ex);
}

// normalize + bias + ELU.  dst_sel==0: -> g_xcur and re-zero g_out/g_denom.
__global__ void k_fin(const float* __restrict__ bias, int dst_sel) {
    int t = blockIdx.x * blockDim.x + threadIdx.x;
    if (t >= NN * HC) return;
    int n = t >> 5, o = t & 31, h = o >> 4;
    float den = g_denom[n * 2 + h];
    float v = g_out[t] / (den + 1e-16f) + bias[o];
    v = (v > 0.f) ? v : expm1f(v);
    if (dst_sel == 0) {
        g_xcur[t] = v;
        __syncwarp();
        g_out[t] = 0.f;
        if (o < 2) g_denom[n * 2 + o] = 0.f;
    } else {
        g_out[t] = v;
    }
}

// ---------------- pool + head ------------------------------------------------

__global__ void k_zero_pool() {
    int i = blockIdx.x * blockDim.x + threadIdx.x;
    if (i < GG * HC) g_sums[i] = 0.f;
    if (i < GG)      g_cnt[i]  = 0.f;
}

__global__ void k_pool4(const int* __restrict__ batch) {
    int t = blockIdx.x * blockDim.x + threadIdx.x;
    if (t >= NN * 8) return;
    int n = t >> 3, j = t & 7;
    int g = batch[n];
    const float4* out4 = (const float4*)g_out;
    float4 vv = out4[n * 8 + j];
    asm volatile("red.global.add.v4.f32 [%0], {%1,%2,%3,%4};"
                 :: "l"(&g_sums[g * HC + 4 * j]),
                    "f"(vv.x), "f"(vv.y), "f"(vv.z), "f"(vv.w) : "memory");
    if (j == 0) atomicAdd(&g_cnt[g], 1.f);
}

__global__ void k_head(const float* __restrict__ Wfc, const float* __restrict__ bfc,
                       float* __restrict__ out) {
    int g = blockIdx.x * blockDim.x + threadIdx.x;
    if (g >= GG) return;
    float inv = 1.f / fmaxf(g_cnt[g], 1.f);
    float l0 = bfc[0], l1 = bfc[1];
#pragma unroll
    for (int k = 0; k < HC; k++) {
        float p = g_sums[g * HC + k] * inv;
        l0 += Wfc[k] * p;
        l1 += Wfc[HC + k] * p;
    }
    float mx  = fmaxf(l0, l1);
    float lse = mx + logf(expf(l0 - mx) + expf(l1 - mx));
    out[g * 2 + 0] = l0 - lse;
    out[g * 2 + 1] = l1 - lse;
}

// ---------------- launch -----------------------------------------------------

extern "C" void kernel_launch(void* const* d_in, const int* in_sizes, int n_in,
                              void* d_out, int out_size) {
    const int* ei    = (const int*)d_in[0];
    const int* batch = (const int*)d_in[1];
    const float* rand_feat = (const float*)d_in[2];
    const float* W1l = (const float*)d_in[3];
    const float* b1l = (const float*)d_in[4];
    const float* W1r = (const float*)d_in[5];
    const float* b1r = (const float*)d_in[6];
    const float* att1 = (const float*)d_in[7];
    const float* bias1 = (const float*)d_in[8];
    const float* W2l = (const float*)d_in[9];
    const float* b2l = (const float*)d_in[10];
    const float* W2r = (const float*)d_in[11];
    const float* b2r = (const float*)d_in[12];
    const float* att2 = (const float*)d_in[13];
    const float* bias2 = (const float*)d_in[14];
    const float* Wfc = (const float*)d_in[15];
    const float* bfc = (const float*)d_in[16];
    float* out = (float*)d_out;

    const int B = 256;
    const int gNode   = div_up(NN, B);
    const int gEdge   = div_up(EE, B);
    const int gNodeHC = div_up(NN * HC, B);
    const int gEdge4  = div_up(ETOT * 4, B);

    // prep
    k_zero<<<gNode, B>>>();
    k_degree<<<gEdge, B>>>(ei);
    k_sd<<<div_up(ETOT, B), B>>>(ei);

    // ---- conv1 ----
    k_lin3<<<gNodeHC, B>>>(rand_feat, W1l, b1l, W1r, b1r);   // also zeroes out/denom
    k_pq<<<1, 32>>>(att1);
    k_conv_fused<<<gEdge4, B>>>();
    k_fin<<<gNodeHC, B>>>(bias1, 0);   // -> g_xcur, re-zeroes out/denom

    // ---- conv2 ----
    k_lin32<<<gNodeHC, B>>>(W2l, b2l, W2r, b2r);
    k_pq<<<1, 32>>>(att2);
    k_conv_fused<<<gEdge4, B>>>();
    k_fin<<<gNodeHC, B>>>(bias2, 1);   // -> g_out in place

    // ---- pool + head ----
    k_zero_pool<<<div_up(GG * HC, B), B>>>();
    k_pool4<<<div_up(NN * 8, B), B>>>(batch);
    k_head<<<div_up(GG, B), B>>>(Wfc, bfc, out);
}